// round 2
// baseline (speedup 1.0000x reference)
#include <cuda_runtime.h>
#include <math.h>

#define NN   2000
#define NE   6000
#define E2   8000     // NE + NN self loops
#define FIN  64
#define C1   256      // HEADS1*HID
#define H1   4
#define NA   6001     // NUM_ACTIONS

// ---------------- scratch (device globals; no allocation allowed) ------------
__device__ float g_cnt[NN];
__device__ float g_asum[NN];
__device__ float g_loop[NN];
__device__ int   g_deg[NN];
__device__ int   g_rowptr[NN + 1];
__device__ int   g_cursor[NN];
__device__ int   g_eidx[E2];
__device__ int   g_srcA[E2];
__device__ int   g_dstA[E2];
__device__ float g_ea[E2];
__device__ float g_xl1[NN * C1];
__device__ float g_xr1[NN * C1];
__device__ float g_h1[NN * C1];
__device__ float g_logit1[E2 * H1];
__device__ float g_w1[E2 * H1];
__device__ float g_xl2[(size_t)NN * NA];
__device__ float g_xr2[(size_t)NN * NA];
__device__ float g_logit2[E2];
__device__ float g_w2[E2];
__device__ float g_pooled[NA];

// ---------------- helpers ----------------------------------------------------
__device__ __forceinline__ float lrelu02(float v) { return v > 0.f ? v : 0.2f * v; }

// ---------------- kernels ----------------------------------------------------
__global__ void k_init() {
    int i = blockIdx.x * blockDim.x + threadIdx.x;
    if (i < NN) { g_cnt[i] = 0.f; g_asum[i] = 0.f; g_deg[i] = 0; g_cursor[i] = 0; }
    if (i < NA) g_pooled[i] = 0.f;
}

__global__ void k_edge_stats(const int* __restrict__ ei,
                             const float* __restrict__ eattr) {
    int e = blockIdx.x * blockDim.x + threadIdx.x;
    if (e < NE) {
        int d = ei[NE + e];
        atomicAdd(&g_cnt[d], 1.f);
        atomicAdd(&g_asum[d], eattr[e]);
    }
}

__global__ void k_loop_attr() {
    int i = blockIdx.x * blockDim.x + threadIdx.x;
    if (i < NN) g_loop[i] = g_asum[i] / fmaxf(g_cnt[i], 1.f);
}

__global__ void k_build(const int* __restrict__ ei,
                        const float* __restrict__ eattr) {
    int e = blockIdx.x * blockDim.x + threadIdx.x;
    if (e >= E2) return;
    int s, d; float ea;
    if (e < NE) { s = ei[e]; d = ei[NE + e]; ea = eattr[e]; }
    else        { s = d = e - NE; ea = g_loop[e - NE]; }
    g_srcA[e] = s; g_dstA[e] = d; g_ea[e] = ea;
    atomicAdd(&g_deg[d], 1);
}

__global__ void k_scan() {          // single block, 1024 threads, 2 elems/thread
    __shared__ int s[1024];
    int t = threadIdx.x;
    int a0 = (2 * t     < NN) ? g_deg[2 * t]     : 0;
    int a1 = (2 * t + 1 < NN) ? g_deg[2 * t + 1] : 0;
    s[t] = a0 + a1;
    __syncthreads();
    for (int off = 1; off < 1024; off <<= 1) {
        int v = s[t] + (t >= off ? s[t - off] : 0);
        __syncthreads();
        s[t] = v;
        __syncthreads();
    }
    int excl = t ? s[t - 1] : 0;
    if (2 * t     < NN) g_rowptr[2 * t]     = excl;
    if (2 * t + 1 < NN) g_rowptr[2 * t + 1] = excl + a0;
    if (t == 0) g_rowptr[NN] = s[1023];
}

__global__ void k_scatter() {
    int e = blockIdx.x * blockDim.x + threadIdx.x;
    if (e < E2) {
        int d = g_dstA[e];
        int pos = g_rowptr[d] + atomicAdd(&g_cursor[d], 1);
        g_eidx[pos] = e;
    }
}

// layer-1 transforms: xl1/xr1 = x @ W^T + b,  W:[256,64]
__global__ void k_gemm1(const float* __restrict__ x,
                        const float* __restrict__ Wl, const float* __restrict__ bl,
                        const float* __restrict__ Wr, const float* __restrict__ br) {
    const float* W = blockIdx.y ? Wr : Wl;
    const float* b = blockIdx.y ? br : bl;
    float* out     = blockIdx.y ? g_xr1 : g_xl1;
    __shared__ float xs[16][FIN];
    int t = threadIdx.x;
    int n0 = blockIdx.x * 16;
    for (int i = t; i < 16 * FIN; i += 256)
        xs[i / FIN][i % FIN] = x[(n0 + i / FIN) * FIN + (i % FIN)];
    __syncthreads();
    float acc[16];
    #pragma unroll
    for (int i = 0; i < 16; i++) acc[i] = 0.f;
    const float* wrow = W + t * FIN;
    for (int k = 0; k < FIN; k++) {
        float w = wrow[k];
        #pragma unroll
        for (int i = 0; i < 16; i++) acc[i] += xs[i][k] * w;
    }
    float bb = b[t];
    #pragma unroll
    for (int i = 0; i < 16; i++) out[(n0 + i) * C1 + t] = acc[i] + bb;
}

// layer-1 edge logits: warp per edge
__global__ void k_logits1(const float* __restrict__ We1,
                          const float* __restrict__ att1) {
    int e = blockIdx.x * 8 + (threadIdx.x >> 5);
    int lane = threadIdx.x & 31;
    if (e >= E2) return;
    int s = g_srcA[e], d = g_dstA[e];
    float ea = g_ea[e];
    const float* xl = g_xl1 + s * C1;
    const float* xr = g_xr1 + d * C1;
    float acc[H1] = {0.f, 0.f, 0.f, 0.f};
    for (int idx = lane; idx < C1; idx += 32) {
        float v = lrelu02(xl[idx] + xr[idx] + ea * We1[idx]);
        acc[idx >> 6] += v * att1[idx];
    }
    #pragma unroll
    for (int h = 0; h < H1; h++) {
        float v = acc[h];
        for (int o = 16; o; o >>= 1) v += __shfl_xor_sync(0xffffffffu, v, o);
        if (lane == 0) g_logit1[e * H1 + h] = v;
    }
}

__global__ void k_softmax1() {      // warp per node
    int n = blockIdx.x, lane = threadIdx.x;
    int rp = g_rowptr[n], deg = g_rowptr[n + 1] - rp;
    for (int h = 0; h < H1; h++) {
        float m = -1e30f;
        for (int i = lane; i < deg; i += 32)
            m = fmaxf(m, g_logit1[g_eidx[rp + i] * H1 + h]);
        for (int o = 16; o; o >>= 1) m = fmaxf(m, __shfl_xor_sync(0xffffffffu, m, o));
        float s = 0.f;
        for (int i = lane; i < deg; i += 32)
            s += expf(g_logit1[g_eidx[rp + i] * H1 + h] - m);
        for (int o = 16; o; o >>= 1) s += __shfl_xor_sync(0xffffffffu, s, o);
        float inv = 1.f / (s + 1e-16f);
        for (int i = lane; i < deg; i += 32) {
            int e = g_eidx[rp + i];
            g_w1[e * H1 + h] = expf(g_logit1[e * H1 + h] - m) * inv;
        }
    }
}

__global__ void k_agg1(const float* __restrict__ b1) {   // block per node, 256 thr
    int n = blockIdx.x, c = threadIdx.x;
    int rp = g_rowptr[n], re = g_rowptr[n + 1];
    int h = c >> 6;
    float acc = 0.f;
    for (int i = rp; i < re; i++) {
        int e = g_eidx[i];
        acc += g_w1[e * H1 + h] * g_xl1[g_srcA[e] * C1 + c];
    }
    acc += b1[c];
    g_h1[n * C1 + c] = acc > 0.f ? acc : 0.f;
}

// layer-2 transforms: xl2/xr2 = h1[2000,256] @ W[6001,256]^T + b  (NT gemm)
__global__ void k_gemm2(const float* __restrict__ Wl, const float* __restrict__ bl,
                        const float* __restrict__ Wr, const float* __restrict__ br) {
    const float* W    = blockIdx.z ? Wr : Wl;
    const float* bias = blockIdx.z ? br : bl;
    float* C          = blockIdx.z ? g_xr2 : g_xl2;
    __shared__ float As[64][17];
    __shared__ float Bs[64][17];
    int t = threadIdx.x;
    int tx = t & 15, ty = t >> 4;
    int m0 = blockIdx.y * 64, n0 = blockIdx.x * 64;
    float acc[4][4] = {};
    for (int k0 = 0; k0 < C1; k0 += 16) {
        for (int i = t; i < 64 * 16; i += 256) {
            int r = i >> 4, c = i & 15;
            int gm = m0 + r;
            As[r][c] = (gm < NN) ? g_h1[gm * C1 + k0 + c] : 0.f;
            int gn = n0 + r;
            Bs[r][c] = (gn < NA) ? W[gn * C1 + k0 + c] : 0.f;
        }
        __syncthreads();
        #pragma unroll
        for (int kk = 0; kk < 16; kk++) {
            float av[4], bv[4];
            #pragma unroll
            for (int i = 0; i < 4; i++) av[i] = As[ty * 4 + i][kk];
            #pragma unroll
            for (int j = 0; j < 4; j++) bv[j] = Bs[tx * 4 + j][kk];
            #pragma unroll
            for (int i = 0; i < 4; i++)
                #pragma unroll
                for (int j = 0; j < 4; j++)
                    acc[i][j] += av[i] * bv[j];
        }
        __syncthreads();
    }
    #pragma unroll
    for (int i = 0; i < 4; i++) {
        int gm = m0 + ty * 4 + i;
        if (gm >= NN) continue;
        #pragma unroll
        for (int j = 0; j < 4; j++) {
            int gn = n0 + tx * 4 + j;
            if (gn < NA) C[(size_t)gm * NA + gn] = acc[i][j] + bias[gn];
        }
    }
}

// layer-2 edge logits: block per edge, dot over 6001 channels
__global__ void k_logits2(const float* __restrict__ We2,
                          const float* __restrict__ att2) {
    int e = blockIdx.x, t = threadIdx.x;
    int s = g_srcA[e], d = g_dstA[e];
    float ea = g_ea[e];
    const float* xl = g_xl2 + (size_t)s * NA;
    const float* xr = g_xr2 + (size_t)d * NA;
    float acc = 0.f;
    for (int a = t; a < NA; a += 256) {
        float v = lrelu02(xl[a] + xr[a] + ea * We2[a]);
        acc += v * att2[a];
    }
    float v = acc;
    for (int o = 16; o; o >>= 1) v += __shfl_xor_sync(0xffffffffu, v, o);
    __shared__ float red[8];
    if ((t & 31) == 0) red[t >> 5] = v;
    __syncthreads();
    if (t < 8) {
        float r = red[t];
        for (int o = 4; o; o >>= 1) r += __shfl_xor_sync(0xffu, r, o);
        if (t == 0) g_logit2[e] = r;
    }
}

__global__ void k_softmax2() {      // warp per node
    int n = blockIdx.x, lane = threadIdx.x;
    int rp = g_rowptr[n], deg = g_rowptr[n + 1] - rp;
    float m = -1e30f;
    for (int i = lane; i < deg; i += 32)
        m = fmaxf(m, g_logit2[g_eidx[rp + i]]);
    for (int o = 16; o; o >>= 1) m = fmaxf(m, __shfl_xor_sync(0xffffffffu, m, o));
    float s = 0.f;
    for (int i = lane; i < deg; i += 32)
        s += expf(g_logit2[g_eidx[rp + i]] - m);
    for (int o = 16; o; o >>= 1) s += __shfl_xor_sync(0xffffffffu, s, o);
    float inv = 1.f / (s + 1e-16f);
    for (int i = lane; i < deg; i += 32) {
        int e = g_eidx[rp + i];
        g_w2[e] = expf(g_logit2[e] - m) * inv;
    }
}

// aggregation + bias + relu + mean-pool accumulation (h2 never materialized)
__global__ void k_agg2(const float* __restrict__ b2) {   // block per node
    int n = blockIdx.x, t = threadIdx.x;
    int rp = g_rowptr[n], re = g_rowptr[n + 1];
    for (int a = t; a < NA; a += 256) {
        float acc = 0.f;
        for (int i = rp; i < re; i++) {
            int e = g_eidx[i];
            acc += g_w2[e] * g_xl2[(size_t)g_srcA[e] * NA + a];
        }
        float v = acc + b2[a];
        v = v > 0.f ? v : 0.f;
        atomicAdd(&g_pooled[a], v);
    }
}

__global__ void k_final(const float* __restrict__ alpha, float* __restrict__ out,
                        int out_size) {
    __shared__ float red[32];
    int t = threadIdx.x;
    const float invN = 1.f / (float)NN;
    float m = -1e30f;
    for (int a = t; a < NA; a += 1024) m = fmaxf(m, g_pooled[a] * invN);
    for (int o = 16; o; o >>= 1) m = fmaxf(m, __shfl_xor_sync(0xffffffffu, m, o));
    if ((t & 31) == 0) red[t >> 5] = m;
    __syncthreads();
    if (t < 32) {
        float r = red[t];
        for (int o = 16; o; o >>= 1) r = fmaxf(r, __shfl_xor_sync(0xffffffffu, r, o));
        if (t == 0) red[0] = r;
    }
    __syncthreads();
    m = red[0];
    __syncthreads();
    float s = 0.f;
    for (int a = t; a < NA; a += 1024) s += expf(g_pooled[a] * invN - m);
    for (int o = 16; o; o >>= 1) s += __shfl_xor_sync(0xffffffffu, s, o);
    if ((t & 31) == 0) red[t >> 5] = s;
    __syncthreads();
    if (t < 32) {
        float r = red[t];
        for (int o = 16; o; o >>= 1) r += __shfl_xor_sync(0xffffffffu, r, o);
        if (t == 0) red[0] = r;
    }
    __syncthreads();
    float invS = 1.f / red[0];
    for (int a = t; a < NA; a += 1024)
        out[a] = expf(g_pooled[a] * invN - m) * invS;
    if (t == 0 && out_size > NA)
        out[NA] = 1.f / (1.f + expf(-alpha[0]));
}

// ---------------- launch ------------------------------------------------------
extern "C" void kernel_launch(void* const* d_in, const int* in_sizes, int n_in,
                              void* d_out, int out_size) {
    const float* x     = (const float*)d_in[0];
    const int*   ei    = (const int*)d_in[1];      // int32! (JAX without x64)
    const float* eattr = (const float*)d_in[2];
    const float* alpha = (const float*)d_in[3];
    const float* Wl1 = (const float*)d_in[4];
    const float* bl1 = (const float*)d_in[5];
    const float* Wr1 = (const float*)d_in[6];
    const float* br1 = (const float*)d_in[7];
    const float* We1 = (const float*)d_in[8];
    const float* att1= (const float*)d_in[9];
    const float* b1  = (const float*)d_in[10];
    const float* Wl2 = (const float*)d_in[11];
    const float* bl2 = (const float*)d_in[12];
    const float* Wr2 = (const float*)d_in[13];
    const float* br2 = (const float*)d_in[14];
    const float* We2 = (const float*)d_in[15];
    const float* att2= (const float*)d_in[16];
    const float* b2  = (const float*)d_in[17];
    float* out = (float*)d_out;

    k_init      <<<(NA + 255) / 256, 256>>>();
    k_edge_stats<<<(NE + 255) / 256, 256>>>(ei, eattr);
    k_loop_attr <<<(NN + 255) / 256, 256>>>();
    k_build     <<<(E2 + 255) / 256, 256>>>(ei, eattr);
    k_scan      <<<1, 1024>>>();
    k_scatter   <<<(E2 + 255) / 256, 256>>>();
    k_gemm1     <<<dim3(NN / 16, 2), 256>>>(x, Wl1, bl1, Wr1, br1);
    k_logits1   <<<(E2 + 7) / 8, 256>>>(We1, att1);
    k_softmax1  <<<NN, 32>>>();
    k_agg1      <<<NN, 256>>>(b1);
    k_gemm2     <<<dim3((NA + 63) / 64, (NN + 63) / 64, 2), 256>>>(Wl2, bl2, Wr2, br2);
    k_logits2   <<<E2, 256>>>(We2, att2);
    k_softmax2  <<<NN, 32>>>();
    k_agg2      <<<NN, 256>>>(b2);
    k_final     <<<1, 1024>>>(alpha, out, out_size);
}

// round 3
// speedup vs baseline: 1.5062x; 1.5062x over previous
#include <cuda_runtime.h>
#include <math.h>

#define NN   2000
#define NE   6000
#define E2   8000     // NE + NN self loops
#define FIN  64
#define C1   256      // HEADS1*HID
#define H1   4
#define NA   6001     // NUM_ACTIONS

// ---------------- scratch (device globals; no allocation allowed) ------------
__device__ float g_cnt[NN];
__device__ float g_asum[NN];
__device__ float g_loop[NN];
__device__ int   g_deg[NN];
__device__ int   g_rowptr[NN + 1];
__device__ int   g_cursor[NN];
__device__ int   g_eidx[E2];
__device__ int   g_srcA[E2];
__device__ int   g_dstA[E2];
__device__ float g_ea[E2];
__device__ float g_xl1[NN * C1];
__device__ float g_xr1[NN * C1];
__device__ float g_h1[NN * C1];
__device__ float g_logit1[E2 * H1];
__device__ float g_w1[E2 * H1];
__device__ float g_xl2[(size_t)NN * NA];
__device__ float g_xr2[(size_t)NN * NA];
__device__ float g_logit2[E2];
__device__ float g_w2[E2];
__device__ float g_pooled[NA];

// ---------------- helpers ----------------------------------------------------
__device__ __forceinline__ float lrelu02(float v) { return v > 0.f ? v : 0.2f * v; }

__device__ __forceinline__ void mma8(float c[4],
                                     unsigned a0, unsigned a1, unsigned a2, unsigned a3,
                                     unsigned b0, unsigned b1) {
    asm volatile(
        "mma.sync.aligned.m16n8k8.row.col.f32.tf32.tf32.f32 "
        "{%0,%1,%2,%3}, {%4,%5,%6,%7}, {%8,%9}, {%0,%1,%2,%3};\n"
        : "+f"(c[0]), "+f"(c[1]), "+f"(c[2]), "+f"(c[3])
        : "r"(a0), "r"(a1), "r"(a2), "r"(a3), "r"(b0), "r"(b1));
}

// ---------------- kernels ----------------------------------------------------
__global__ void k_init() {
    int i = blockIdx.x * blockDim.x + threadIdx.x;
    if (i < NN) { g_cnt[i] = 0.f; g_asum[i] = 0.f; g_deg[i] = 0; g_cursor[i] = 0; }
    if (i < NA) g_pooled[i] = 0.f;
}

__global__ void k_edge_stats(const int* __restrict__ ei,
                             const float* __restrict__ eattr) {
    int e = blockIdx.x * blockDim.x + threadIdx.x;
    if (e < NE) {
        int d = ei[NE + e];
        atomicAdd(&g_cnt[d], 1.f);
        atomicAdd(&g_asum[d], eattr[e]);
    }
}

__global__ void k_loop_attr() {
    int i = blockIdx.x * blockDim.x + threadIdx.x;
    if (i < NN) g_loop[i] = g_asum[i] / fmaxf(g_cnt[i], 1.f);
}

__global__ void k_build(const int* __restrict__ ei,
                        const float* __restrict__ eattr) {
    int e = blockIdx.x * blockDim.x + threadIdx.x;
    if (e >= E2) return;
    int s, d; float ea;
    if (e < NE) { s = ei[e]; d = ei[NE + e]; ea = eattr[e]; }
    else        { s = d = e - NE; ea = g_loop[e - NE]; }
    g_srcA[e] = s; g_dstA[e] = d; g_ea[e] = ea;
    atomicAdd(&g_deg[d], 1);
}

__global__ void k_scan() {          // single block, 1024 threads, 2 elems/thread
    __shared__ int s[1024];
    int t = threadIdx.x;
    int a0 = (2 * t     < NN) ? g_deg[2 * t]     : 0;
    int a1 = (2 * t + 1 < NN) ? g_deg[2 * t + 1] : 0;
    s[t] = a0 + a1;
    __syncthreads();
    for (int off = 1; off < 1024; off <<= 1) {
        int v = s[t] + (t >= off ? s[t - off] : 0);
        __syncthreads();
        s[t] = v;
        __syncthreads();
    }
    int excl = t ? s[t - 1] : 0;
    if (2 * t     < NN) g_rowptr[2 * t]     = excl;
    if (2 * t + 1 < NN) g_rowptr[2 * t + 1] = excl + a0;
    if (t == 0) g_rowptr[NN] = s[1023];
}

__global__ void k_scatter() {
    int e = blockIdx.x * blockDim.x + threadIdx.x;
    if (e < E2) {
        int d = g_dstA[e];
        int pos = g_rowptr[d] + atomicAdd(&g_cursor[d], 1);
        g_eidx[pos] = e;
    }
}

// layer-1 transforms: xl1/xr1 = x @ W^T + b,  W:[256,64]
__global__ void k_gemm1(const float* __restrict__ x,
                        const float* __restrict__ Wl, const float* __restrict__ bl,
                        const float* __restrict__ Wr, const float* __restrict__ br) {
    const float* W = blockIdx.y ? Wr : Wl;
    const float* b = blockIdx.y ? br : bl;
    float* out     = blockIdx.y ? g_xr1 : g_xl1;
    __shared__ float xs[16][FIN];
    int t = threadIdx.x;
    int n0 = blockIdx.x * 16;
    for (int i = t; i < 16 * FIN; i += 256)
        xs[i / FIN][i % FIN] = x[(n0 + i / FIN) * FIN + (i % FIN)];
    __syncthreads();
    float acc[16];
    #pragma unroll
    for (int i = 0; i < 16; i++) acc[i] = 0.f;
    const float* wrow = W + t * FIN;
    for (int k = 0; k < FIN; k++) {
        float w = wrow[k];
        #pragma unroll
        for (int i = 0; i < 16; i++) acc[i] += xs[i][k] * w;
    }
    float bb = b[t];
    #pragma unroll
    for (int i = 0; i < 16; i++) out[(n0 + i) * C1 + t] = acc[i] + bb;
}

// layer-1 edge logits: warp per edge
__global__ void k_logits1(const float* __restrict__ We1,
                          const float* __restrict__ att1) {
    int e = blockIdx.x * 8 + (threadIdx.x >> 5);
    int lane = threadIdx.x & 31;
    if (e >= E2) return;
    int s = g_srcA[e], d = g_dstA[e];
    float ea = g_ea[e];
    const float* xl = g_xl1 + s * C1;
    const float* xr = g_xr1 + d * C1;
    float acc[H1] = {0.f, 0.f, 0.f, 0.f};
    for (int idx = lane; idx < C1; idx += 32) {
        float v = lrelu02(xl[idx] + xr[idx] + ea * We1[idx]);
        acc[idx >> 6] += v * att1[idx];
    }
    #pragma unroll
    for (int h = 0; h < H1; h++) {
        float v = acc[h];
        for (int o = 16; o; o >>= 1) v += __shfl_xor_sync(0xffffffffu, v, o);
        if (lane == 0) g_logit1[e * H1 + h] = v;
    }
}

__global__ void k_softmax1() {      // warp per node
    int n = blockIdx.x, lane = threadIdx.x;
    int rp = g_rowptr[n], deg = g_rowptr[n + 1] - rp;
    for (int h = 0; h < H1; h++) {
        float m = -1e30f;
        for (int i = lane; i < deg; i += 32)
            m = fmaxf(m, g_logit1[g_eidx[rp + i] * H1 + h]);
        for (int o = 16; o; o >>= 1) m = fmaxf(m, __shfl_xor_sync(0xffffffffu, m, o));
        float s = 0.f;
        for (int i = lane; i < deg; i += 32)
            s += expf(g_logit1[g_eidx[rp + i] * H1 + h] - m);
        for (int o = 16; o; o >>= 1) s += __shfl_xor_sync(0xffffffffu, s, o);
        float inv = 1.f / (s + 1e-16f);
        for (int i = lane; i < deg; i += 32) {
            int e = g_eidx[rp + i];
            g_w1[e * H1 + h] = expf(g_logit1[e * H1 + h] - m) * inv;
        }
    }
}

__global__ void k_agg1(const float* __restrict__ b1) {   // block per node, 256 thr
    int n = blockIdx.x, c = threadIdx.x;
    int rp = g_rowptr[n], re = g_rowptr[n + 1];
    int h = c >> 6;
    float acc = 0.f;
    for (int i = rp; i < re; i++) {
        int e = g_eidx[i];
        acc += g_w1[e * H1 + h] * g_xl1[g_srcA[e] * C1 + c];
    }
    acc += b1[c];
    g_h1[n * C1 + c] = acc > 0.f ? acc : 0.f;
}

// ---------------------------------------------------------------------------
// layer-2 transforms via 3xTF32 tensor-core GEMM:
//   xl2/xr2[2000,6001] = h1[2000,256] @ W[6001,256]^T + b    (NT)
// 128x128 block tile, 8 warps (64x32 each), mma.m16n8k8, hi/lo split in smem.
// ---------------------------------------------------------------------------
__global__ void __launch_bounds__(256) k_gemm2(
        const float* __restrict__ Wl, const float* __restrict__ bl,
        const float* __restrict__ Wr, const float* __restrict__ br) {
    const float* W    = blockIdx.z ? Wr : Wl;
    const float* bias = blockIdx.z ? br : bl;
    float* C          = blockIdx.z ? g_xr2 : g_xl2;

    __shared__ float As_hi[128][20];
    __shared__ float As_lo[128][20];
    __shared__ float Bs_hi[128][20];
    __shared__ float Bs_lo[128][20];

    const int t    = threadIdx.x;
    const int wid  = t >> 5;
    const int lane = t & 31;
    const int wm   = wid & 1;        // 0..1  (64-row slab)
    const int wn   = wid >> 1;       // 0..3  (32-col slab)
    const int gq   = lane >> 2;      // groupID 0..7
    const int q    = lane & 3;       // 0..3
    const int m0   = blockIdx.y * 128;
    const int n0   = blockIdx.x * 128;

    float acc[4][4][4];
    #pragma unroll
    for (int i = 0; i < 4; i++)
        #pragma unroll
        for (int j = 0; j < 4; j++)
            #pragma unroll
            for (int k = 0; k < 4; k++) acc[i][j][k] = 0.f;

    const int fr = t >> 2;           // 0..63 (fill row)
    const int fk = (t & 3) * 4;      // 0,4,8,12

    for (int k0 = 0; k0 < C1; k0 += 16) {
        // ---- fill A and B tiles (128x16 each), hi/lo split -----------------
        #pragma unroll
        for (int half = 0; half < 2; half++) {
            int r = fr + half * 64;
            // A = h1 rows
            float4 va = make_float4(0.f, 0.f, 0.f, 0.f);
            int gm = m0 + r;
            if (gm < NN) va = *(const float4*)&g_h1[gm * C1 + k0 + fk];
            // B = W rows
            float4 vb = make_float4(0.f, 0.f, 0.f, 0.f);
            int gn = n0 + r;
            if (gn < NA) vb = *(const float4*)&W[gn * C1 + k0 + fk];
            const float* pa = &va.x;
            const float* pb = &vb.x;
            #pragma unroll
            for (int j = 0; j < 4; j++) {
                float a  = pa[j];
                float ah = __uint_as_float(__float_as_uint(a) & 0xFFFFE000u);
                As_hi[r][fk + j] = ah;
                As_lo[r][fk + j] = a - ah;
                float b  = pb[j];
                float bh = __uint_as_float(__float_as_uint(b) & 0xFFFFE000u);
                Bs_hi[r][fk + j] = bh;
                Bs_lo[r][fk + j] = b - bh;
            }
        }
        __syncthreads();

        // ---- two k8 steps ---------------------------------------------------
        #pragma unroll
        for (int ks = 0; ks < 16; ks += 8) {
            unsigned ah[4][4], al[4][4], bh[4][2], bl[4][2];
            #pragma unroll
            for (int mt = 0; mt < 4; mt++) {
                int row = wm * 64 + mt * 16;
                ah[mt][0] = __float_as_uint(As_hi[row + gq    ][ks + q    ]);
                ah[mt][1] = __float_as_uint(As_hi[row + gq + 8][ks + q    ]);
                ah[mt][2] = __float_as_uint(As_hi[row + gq    ][ks + q + 4]);
                ah[mt][3] = __float_as_uint(As_hi[row + gq + 8][ks + q + 4]);
                al[mt][0] = __float_as_uint(As_lo[row + gq    ][ks + q    ]);
                al[mt][1] = __float_as_uint(As_lo[row + gq + 8][ks + q    ]);
                al[mt][2] = __float_as_uint(As_lo[row + gq    ][ks + q + 4]);
                al[mt][3] = __float_as_uint(As_lo[row + gq + 8][ks + q + 4]);
            }
            #pragma unroll
            for (int nt = 0; nt < 4; nt++) {
                int col = wn * 32 + nt * 8 + gq;
                bh[nt][0] = __float_as_uint(Bs_hi[col][ks + q    ]);
                bh[nt][1] = __float_as_uint(Bs_hi[col][ks + q + 4]);
                bl[nt][0] = __float_as_uint(Bs_lo[col][ks + q    ]);
                bl[nt][1] = __float_as_uint(Bs_lo[col][ks + q + 4]);
            }
            #pragma unroll
            for (int mt = 0; mt < 4; mt++)
                #pragma unroll
                for (int nt = 0; nt < 4; nt++) {
                    mma8(acc[mt][nt], ah[mt][0], ah[mt][1], ah[mt][2], ah[mt][3],
                         bh[nt][0], bh[nt][1]);
                    mma8(acc[mt][nt], ah[mt][0], ah[mt][1], ah[mt][2], ah[mt][3],
                         bl[nt][0], bl[nt][1]);
                    mma8(acc[mt][nt], al[mt][0], al[mt][1], al[mt][2], al[mt][3],
                         bh[nt][0], bh[nt][1]);
                }
        }
        __syncthreads();
    }

    // ---- epilogue: bias + store ---------------------------------------------
    #pragma unroll
    for (int mt = 0; mt < 4; mt++) {
        int r0 = m0 + wm * 64 + mt * 16 + gq;
        #pragma unroll
        for (int nt = 0; nt < 4; nt++) {
            int c0 = n0 + wn * 32 + nt * 8 + q * 2;
            if (c0 < NA) {
                float bv0 = bias[c0];
                float bv1 = (c0 + 1 < NA) ? bias[c0 + 1] : 0.f;
                if (r0 < NN) {
                    C[(size_t)r0 * NA + c0] = acc[mt][nt][0] + bv0;
                    if (c0 + 1 < NA) C[(size_t)r0 * NA + c0 + 1] = acc[mt][nt][1] + bv1;
                }
                if (r0 + 8 < NN) {
                    C[(size_t)(r0 + 8) * NA + c0] = acc[mt][nt][2] + bv0;
                    if (c0 + 1 < NA) C[(size_t)(r0 + 8) * NA + c0 + 1] = acc[mt][nt][3] + bv1;
                }
            }
        }
    }
}

// layer-2 edge logits: block per edge, dot over 6001 channels
__global__ void k_logits2(const float* __restrict__ We2,
                          const float* __restrict__ att2) {
    int e = blockIdx.x, t = threadIdx.x;
    int s = g_srcA[e], d = g_dstA[e];
    float ea = g_ea[e];
    const float* xl = g_xl2 + (size_t)s * NA;
    const float* xr = g_xr2 + (size_t)d * NA;
    float acc = 0.f;
    for (int a = t; a < NA; a += 256) {
        float v = lrelu02(xl[a] + xr[a] + ea * We2[a]);
        acc += v * att2[a];
    }
    float v = acc;
    for (int o = 16; o; o >>= 1) v += __shfl_xor_sync(0xffffffffu, v, o);
    __shared__ float red[8];
    if ((t & 31) == 0) red[t >> 5] = v;
    __syncthreads();
    if (t < 8) {
        float r = red[t];
        for (int o = 4; o; o >>= 1) r += __shfl_xor_sync(0xffu, r, o);
        if (t == 0) g_logit2[e] = r;
    }
}

__global__ void k_softmax2() {      // warp per node
    int n = blockIdx.x, lane = threadIdx.x;
    int rp = g_rowptr[n], deg = g_rowptr[n + 1] - rp;
    float m = -1e30f;
    for (int i = lane; i < deg; i += 32)
        m = fmaxf(m, g_logit2[g_eidx[rp + i]]);
    for (int o = 16; o; o >>= 1) m = fmaxf(m, __shfl_xor_sync(0xffffffffu, m, o));
    float s = 0.f;
    for (int i = lane; i < deg; i += 32)
        s += expf(g_logit2[g_eidx[rp + i]] - m);
    for (int o = 16; o; o >>= 1) s += __shfl_xor_sync(0xffffffffu, s, o);
    float inv = 1.f / (s + 1e-16f);
    for (int i = lane; i < deg; i += 32) {
        int e = g_eidx[rp + i];
        g_w2[e] = expf(g_logit2[e] - m) * inv;
    }
}

// aggregation + bias + relu + mean-pool accumulation (h2 never materialized)
__global__ void k_agg2(const float* __restrict__ b2) {   // block per node
    int n = blockIdx.x, t = threadIdx.x;
    int rp = g_rowptr[n], re = g_rowptr[n + 1];
    for (int a = t; a < NA; a += 256) {
        float acc = 0.f;
        for (int i = rp; i < re; i++) {
            int e = g_eidx[i];
            acc += g_w2[e] * g_xl2[(size_t)g_srcA[e] * NA + a];
        }
        float v = acc + b2[a];
        v = v > 0.f ? v : 0.f;
        atomicAdd(&g_pooled[a], v);
    }
}

__global__ void k_final(const float* __restrict__ alpha, float* __restrict__ out,
                        int out_size) {
    __shared__ float red[32];
    int t = threadIdx.x;
    const float invN = 1.f / (float)NN;
    float m = -1e30f;
    for (int a = t; a < NA; a += 1024) m = fmaxf(m, g_pooled[a] * invN);
    for (int o = 16; o; o >>= 1) m = fmaxf(m, __shfl_xor_sync(0xffffffffu, m, o));
    if ((t & 31) == 0) red[t >> 5] = m;
    __syncthreads();
    if (t < 32) {
        float r = red[t];
        for (int o = 16; o; o >>= 1) r = fmaxf(r, __shfl_xor_sync(0xffffffffu, r, o));
        if (t == 0) red[0] = r;
    }
    __syncthreads();
    m = red[0];
    __syncthreads();
    float s = 0.f;
    for (int a = t; a < NA; a += 1024) s += expf(g_pooled[a] * invN - m);
    for (int o = 16; o; o >>= 1) s += __shfl_xor_sync(0xffffffffu, s, o);
    if ((t & 31) == 0) red[t >> 5] = s;
    __syncthreads();
    if (t < 32) {
        float r = red[t];
        for (int o = 16; o; o >>= 1) r += __shfl_xor_sync(0xffffffffu, r, o);
        if (t == 0) red[0] = r;
    }
    __syncthreads();
    float invS = 1.f / red[0];
    for (int a = t; a < NA; a += 1024)
        out[a] = expf(g_pooled[a] * invN - m) * invS;
    if (t == 0 && out_size > NA)
        out[NA] = 1.f / (1.f + expf(-alpha[0]));
}

// ---------------- launch ------------------------------------------------------
extern "C" void kernel_launch(void* const* d_in, const int* in_sizes, int n_in,
                              void* d_out, int out_size) {
    const float* x     = (const float*)d_in[0];
    const int*   ei    = (const int*)d_in[1];      // int32 (JAX default)
    const float* eattr = (const float*)d_in[2];
    const float* alpha = (const float*)d_in[3];
    const float* Wl1 = (const float*)d_in[4];
    const float* bl1 = (const float*)d_in[5];
    const float* Wr1 = (const float*)d_in[6];
    const float* br1 = (const float*)d_in[7];
    const float* We1 = (const float*)d_in[8];
    const float* att1= (const float*)d_in[9];
    const float* b1  = (const float*)d_in[10];
    const float* Wl2 = (const float*)d_in[11];
    const float* bl2 = (const float*)d_in[12];
    const float* Wr2 = (const float*)d_in[13];
    const float* br2 = (const float*)d_in[14];
    const float* We2 = (const float*)d_in[15];
    const float* att2= (const float*)d_in[16];
    const float* b2  = (const float*)d_in[17];
    float* out = (float*)d_out;

    k_init      <<<(NA + 255) / 256, 256>>>();
    k_edge_stats<<<(NE + 255) / 256, 256>>>(ei, eattr);
    k_loop_attr <<<(NN + 255) / 256, 256>>>();
    k_build     <<<(E2 + 255) / 256, 256>>>(ei, eattr);
    k_scan      <<<1, 1024>>>();
    k_scatter   <<<(E2 + 255) / 256, 256>>>();
    k_gemm1     <<<dim3(NN / 16, 2), 256>>>(x, Wl1, bl1, Wr1, br1);
    k_logits1   <<<(E2 + 7) / 8, 256>>>(We1, att1);
    k_softmax1  <<<NN, 32>>>();
    k_agg1      <<<NN, 256>>>(b1);
    k_gemm2     <<<dim3((NA + 127) / 128, (NN + 127) / 128, 2), 256>>>(Wl2, bl2, Wr2, br2);
    k_logits2   <<<E2, 256>>>(We2, att2);
    k_softmax2  <<<NN, 32>>>();
    k_agg2      <<<NN, 256>>>(b2);
    k_final     <<<1, 1024>>>(alpha, out, out_size);
}

// round 5
// speedup vs baseline: 1.9840x; 1.3172x over previous
#include <cuda_runtime.h>
#include <cuda_bf16.h>
#include <math.h>

#define NN   2000
#define NE   6000
#define E2   8000     // NE + NN self loops
#define FIN  64
#define C1   256      // HEADS1*HID
#define H1   4
#define NA   6001     // NUM_ACTIONS
#define MAXD 512      // max in-degree safety bound

// ---------------- scratch (device globals; no allocation allowed) ------------
__device__ float g_cnt[NN];
__device__ float g_asum[NN];
__device__ int   g_deg[NN];
__device__ int   g_rowptr[NN + 1];
__device__ int   g_cursor[NN];
__device__ int   g_eidx[E2];
__device__ int   g_srcA[E2];
__device__ int   g_dstA[E2];
__device__ float g_ea[E2];
__device__ __align__(16) float g_xl1[NN * C1];
__device__ __align__(16) float g_xr1[NN * C1];
__device__ __align__(16) float g_h1[NN * C1];
__device__ __align__(16) float g_xl2[(size_t)NN * NA];
__device__ __align__(16) float g_xr2[(size_t)NN * NA];
__device__ float g_pooled[NA];

// ---------------- helpers ----------------------------------------------------
__device__ __forceinline__ float lrelu02(float v) { return v > 0.f ? v : 0.2f * v; }

__device__ __forceinline__ void mma_bf16(float c[4],
                                         unsigned a0, unsigned a1, unsigned a2, unsigned a3,
                                         unsigned b0, unsigned b1) {
    asm volatile(
        "mma.sync.aligned.m16n8k16.row.col.f32.bf16.bf16.f32 "
        "{%0,%1,%2,%3}, {%4,%5,%6,%7}, {%8,%9}, {%0,%1,%2,%3};\n"
        : "+f"(c[0]), "+f"(c[1]), "+f"(c[2]), "+f"(c[3])
        : "r"(a0), "r"(a1), "r"(a2), "r"(a3), "r"(b0), "r"(b1));
}

__device__ __forceinline__ void split2(float x, float y, unsigned &hi, unsigned &lo) {
    __nv_bfloat16 hx = __float2bfloat16(x);
    __nv_bfloat16 hy = __float2bfloat16(y);
    __nv_bfloat16 lx = __float2bfloat16(x - __bfloat162float(hx));
    __nv_bfloat16 ly = __float2bfloat16(y - __bfloat162float(hy));
    hi = (unsigned)__bfloat16_as_ushort(hx) | ((unsigned)__bfloat16_as_ushort(hy) << 16);
    lo = (unsigned)__bfloat16_as_ushort(lx) | ((unsigned)__bfloat16_as_ushort(ly) << 16);
}

// ---------------- prep kernels ------------------------------------------------
__global__ void k_init() {
    int i = blockIdx.x * blockDim.x + threadIdx.x;
    if (i < NN) { g_cnt[i] = 0.f; g_asum[i] = 0.f; g_deg[i] = 0; g_cursor[i] = 0; }
    if (i < NA) g_pooled[i] = 0.f;
}

__global__ void k_edge_stats(const int* __restrict__ ei,
                             const float* __restrict__ eattr) {
    int e = blockIdx.x * blockDim.x + threadIdx.x;
    if (e < NE) {
        int d = ei[NE + e];
        atomicAdd(&g_cnt[d], 1.f);
        atomicAdd(&g_asum[d], eattr[e]);
    }
}

__global__ void k_build(const int* __restrict__ ei,
                        const float* __restrict__ eattr) {
    int e = blockIdx.x * blockDim.x + threadIdx.x;
    if (e >= E2) return;
    int s, d; float ea;
    if (e < NE) { s = ei[e]; d = ei[NE + e]; ea = eattr[e]; }
    else {
        s = d = e - NE;
        ea = g_asum[s] / fmaxf(g_cnt[s], 1.f);   // mean fill for self-loop
    }
    g_srcA[e] = s; g_dstA[e] = d; g_ea[e] = ea;
    atomicAdd(&g_deg[d], 1);
}

__global__ void k_scan() {          // single block, 1024 threads, 2 elems/thread
    __shared__ int s[1024];
    int t = threadIdx.x;
    int a0 = (2 * t     < NN) ? g_deg[2 * t]     : 0;
    int a1 = (2 * t + 1 < NN) ? g_deg[2 * t + 1] : 0;
    s[t] = a0 + a1;
    __syncthreads();
    for (int off = 1; off < 1024; off <<= 1) {
        int v = s[t] + (t >= off ? s[t - off] : 0);
        __syncthreads();
        s[t] = v;
        __syncthreads();
    }
    int excl = t ? s[t - 1] : 0;
    if (2 * t     < NN) g_rowptr[2 * t]     = excl;
    if (2 * t + 1 < NN) g_rowptr[2 * t + 1] = excl + a0;
    if (t == 0) g_rowptr[NN] = s[1023];
}

__global__ void k_scatter() {
    int e = blockIdx.x * blockDim.x + threadIdx.x;
    if (e < E2) {
        int d = g_dstA[e];
        int pos = g_rowptr[d] + atomicAdd(&g_cursor[d], 1);
        g_eidx[pos] = e;
    }
}

// layer-1 transforms: xl1/xr1 = x @ W^T + b,  W:[256,64]
__global__ void k_gemm1(const float* __restrict__ x,
                        const float* __restrict__ Wl, const float* __restrict__ bl,
                        const float* __restrict__ Wr, const float* __restrict__ br) {
    const float* W = blockIdx.y ? Wr : Wl;
    const float* b = blockIdx.y ? br : bl;
    float* out     = blockIdx.y ? g_xr1 : g_xl1;
    __shared__ float xs[16][FIN];
    int t = threadIdx.x;
    int n0 = blockIdx.x * 16;
    for (int i = t; i < 16 * FIN; i += 256)
        xs[i / FIN][i % FIN] = x[(n0 + i / FIN) * FIN + (i % FIN)];
    __syncthreads();
    float acc[16];
    #pragma unroll
    for (int i = 0; i < 16; i++) acc[i] = 0.f;
    const float* wrow = W + t * FIN;
    for (int k = 0; k < FIN; k++) {
        float w = wrow[k];
        #pragma unroll
        for (int i = 0; i < 16; i++) acc[i] += xs[i][k] * w;
    }
    float bb = b[t];
    #pragma unroll
    for (int i = 0; i < 16; i++) out[(n0 + i) * C1 + t] = acc[i] + bb;
}

// ---------------------------------------------------------------------------
// fused layer-1 attention: logits + segment softmax + aggregation, per node
// block = 256 threads (1 channel each), grid = NN
// ---------------------------------------------------------------------------
__global__ void __launch_bounds__(256) k_attn1(const float* __restrict__ We1,
                                               const float* __restrict__ att1,
                                               const float* __restrict__ b1) {
    int n = blockIdx.x, t = threadIdx.x;
    int wid = t >> 5, lane = t & 31;
    int rp = g_rowptr[n], deg = g_rowptr[n + 1] - rp;

    __shared__ int   ssrc[MAXD];
    __shared__ float sea[MAXD];
    __shared__ float slog[MAXD * H1];
    __shared__ float red8[8];

    for (int i = t; i < deg; i += 256) {
        int e = g_eidx[rp + i];
        ssrc[i] = g_srcA[e];
        sea[i]  = g_ea[e];
    }
    __syncthreads();

    int c = t;                     // channel 0..255
    float xr = g_xr1[n * C1 + c];
    float we = We1[c];
    float at = att1[c];

    for (int i = 0; i < deg; i++) {
        float v = lrelu02(g_xl1[ssrc[i] * C1 + c] + xr + sea[i] * we) * at;
        for (int o = 16; o; o >>= 1) v += __shfl_xor_sync(0xffffffffu, v, o);
        if (lane == 0) red8[wid] = v;
        __syncthreads();
        if (t < H1) slog[i * H1 + t] = red8[2 * t] + red8[2 * t + 1];
        __syncthreads();
    }

    // per-head softmax over deg edges (4 threads, deg small)
    if (t < H1) {
        int h = t;
        float m = -1e30f;
        for (int i = 0; i < deg; i++) m = fmaxf(m, slog[i * H1 + h]);
        float s = 0.f;
        for (int i = 0; i < deg; i++) s += expf(slog[i * H1 + h] - m);
        float inv = 1.f / (s + 1e-16f);
        for (int i = 0; i < deg; i++)
            slog[i * H1 + h] = expf(slog[i * H1 + h] - m) * inv;
    }
    __syncthreads();

    int h = c >> 6;
    float acc = 0.f;
    for (int i = 0; i < deg; i++)
        acc += slog[i * H1 + h] * g_xl1[ssrc[i] * C1 + c];
    acc += b1[c];
    g_h1[n * C1 + c] = acc > 0.f ? acc : 0.f;
}

// ---------------------------------------------------------------------------
// layer-2 transforms via split-bf16 (3-term) tensor-core GEMM:
//   xl2/xr2[2000,6001] = h1[2000,256] @ W[6001,256]^T + b    (NT)
// 128x128 block tile, BK=32, 8 warps (64x32 each), mma.m16n8k16.bf16
// ---------------------------------------------------------------------------
__global__ void __launch_bounds__(256) k_gemm2(
        const float* __restrict__ Wl, const float* __restrict__ bl,
        const float* __restrict__ Wr, const float* __restrict__ br) {
    const float* W    = blockIdx.z ? Wr : Wl;
    const float* bias = blockIdx.z ? br : bl;
    float* C          = blockIdx.z ? g_xr2 : g_xl2;

    // u32-packed bf16 pairs; 16 data u32 per row (=32 bf16), pad to 20
    __shared__ unsigned A_hi[128][20];
    __shared__ unsigned A_lo[128][20];
    __shared__ unsigned B_hi[128][20];
    __shared__ unsigned B_lo[128][20];

    const int t    = threadIdx.x;
    const int wid  = t >> 5;
    const int lane = t & 31;
    const int wm   = wid & 1;        // 0..1  (64-row slab)
    const int wn   = wid >> 1;       // 0..3  (32-col slab)
    const int gq   = lane >> 2;      // 0..7
    const int q    = lane & 3;       // 0..3
    const int m0   = blockIdx.y * 128;
    const int n0   = blockIdx.x * 128;

    float acc[4][4][4];
    #pragma unroll
    for (int i = 0; i < 4; i++)
        #pragma unroll
        for (int j = 0; j < 4; j++)
            #pragma unroll
            for (int k = 0; k < 4; k++) acc[i][j][k] = 0.f;

    const int frow = t >> 3;         // 0..31
    const int fq   = t & 7;          // 0..7 (float4 index within 32 floats)

    for (int k0 = 0; k0 < C1; k0 += 32) {
        // ---- fill (128 rows x 32 floats per tile), split hi/lo --------------
        #pragma unroll
        for (int rr = 0; rr < 4; rr++) {
            int r = frow + rr * 32;
            float4 va = make_float4(0.f, 0.f, 0.f, 0.f);
            int gm = m0 + r;
            if (gm < NN) va = *(const float4*)&g_h1[gm * C1 + k0 + fq * 4];
            float4 vb = make_float4(0.f, 0.f, 0.f, 0.f);
            int gn = n0 + r;
            if (gn < NA) vb = *(const float4*)&W[gn * C1 + k0 + fq * 4];
            unsigned hi, lo;
            split2(va.x, va.y, hi, lo); A_hi[r][fq * 2] = hi;     A_lo[r][fq * 2] = lo;
            split2(va.z, va.w, hi, lo); A_hi[r][fq * 2 + 1] = hi; A_lo[r][fq * 2 + 1] = lo;
            split2(vb.x, vb.y, hi, lo); B_hi[r][fq * 2] = hi;     B_lo[r][fq * 2] = lo;
            split2(vb.z, vb.w, hi, lo); B_hi[r][fq * 2 + 1] = hi; B_lo[r][fq * 2 + 1] = lo;
        }
        __syncthreads();

        // ---- two k16 steps --------------------------------------------------
        #pragma unroll
        for (int ks = 0; ks < 2; ks++) {
            const int b = ks * 8;    // u32 column base
            unsigned ah[4][4], al[4][4], bh[4][2], bl[4][2];
            #pragma unroll
            for (int mt = 0; mt < 4; mt++) {
                int row = wm * 64 + mt * 16;
                ah[mt][0] = A_hi[row + gq    ][b + q];
                ah[mt][1] = A_hi[row + gq + 8][b + q];
                ah[mt][2] = A_hi[row + gq    ][b + q + 4];
                ah[mt][3] = A_hi[row + gq + 8][b + q + 4];
                al[mt][0] = A_lo[row + gq    ][b + q];
                al[mt][1] = A_lo[row + gq + 8][b + q];
                al[mt][2] = A_lo[row + gq    ][b + q + 4];
                al[mt][3] = A_lo[row + gq + 8][b + q + 4];
            }
            #pragma unroll
            for (int nt = 0; nt < 4; nt++) {
                int col = wn * 32 + nt * 8 + gq;
                bh[nt][0] = B_hi[col][b + q];
                bh[nt][1] = B_hi[col][b + q + 4];
                bl[nt][0] = B_lo[col][b + q];
                bl[nt][1] = B_lo[col][b + q + 4];
            }
            #pragma unroll
            for (int mt = 0; mt < 4; mt++)
                #pragma unroll
                for (int nt = 0; nt < 4; nt++) {
                    mma_bf16(acc[mt][nt], ah[mt][0], ah[mt][1], ah[mt][2], ah[mt][3],
                             bh[nt][0], bh[nt][1]);
                    mma_bf16(acc[mt][nt], ah[mt][0], ah[mt][1], ah[mt][2], ah[mt][3],
                             bl[nt][0], bl[nt][1]);
                    mma_bf16(acc[mt][nt], al[mt][0], al[mt][1], al[mt][2], al[mt][3],
                             bh[nt][0], bh[nt][1]);
                }
        }
        __syncthreads();
    }

    // ---- epilogue: bias + store ---------------------------------------------
    #pragma unroll
    for (int mt = 0; mt < 4; mt++) {
        int r0 = m0 + wm * 64 + mt * 16 + gq;
        #pragma unroll
        for (int nt = 0; nt < 4; nt++) {
            int c0 = n0 + wn * 32 + nt * 8 + q * 2;
            if (c0 < NA) {
                float bv0 = bias[c0];
                float bv1 = (c0 + 1 < NA) ? bias[c0 + 1] : 0.f;
                if (r0 < NN) {
                    C[(size_t)r0 * NA + c0] = acc[mt][nt][0] + bv0;
                    if (c0 + 1 < NA) C[(size_t)r0 * NA + c0 + 1] = acc[mt][nt][1] + bv1;
                }
                if (r0 + 8 < NN) {
                    C[(size_t)(r0 + 8) * NA + c0] = acc[mt][nt][2] + bv0;
                    if (c0 + 1 < NA) C[(size_t)(r0 + 8) * NA + c0 + 1] = acc[mt][nt][3] + bv1;
                }
            }
        }
    }
}

// ---------------------------------------------------------------------------
// fused layer-2 attention: logits + segment softmax + aggregation + mean-pool
// block = 256 threads, grid = NN (one block per dst node)
// ---------------------------------------------------------------------------
__global__ void __launch_bounds__(256) k_attn2(const float* __restrict__ We2,
                                               const float* __restrict__ att2,
                                               const float* __restrict__ b2) {
    int n = blockIdx.x, t = threadIdx.x;
    int wid = t >> 5, lane = t & 31;
    int rp = g_rowptr[n], deg = g_rowptr[n + 1] - rp;

    __shared__ int   ssrc[MAXD];
    __shared__ float sea[MAXD];
    __shared__ float slog[MAXD];
    __shared__ float red8[8];

    for (int i = t; i < deg; i += 256) {
        int e = g_eidx[rp + i];
        ssrc[i] = g_srcA[e];
        sea[i]  = g_ea[e];
    }
    __syncthreads();

    const float* xr = g_xr2 + (size_t)n * NA;

    // phase A: logits (xr row becomes L1-resident across edges)
    for (int i = 0; i < deg; i++) {
        const float* xl = g_xl2 + (size_t)ssrc[i] * NA;
        float ea = sea[i];
        float accv = 0.f;
        for (int a = t; a < NA; a += 256) {
            float v = lrelu02(xl[a] + xr[a] + ea * We2[a]);
            accv += v * att2[a];
        }
        for (int o = 16; o; o >>= 1) accv += __shfl_xor_sync(0xffffffffu, accv, o);
        if (lane == 0) red8[wid] = accv;
        __syncthreads();
        if (t == 0) {
            float s = 0.f;
            #pragma unroll
            for (int w = 0; w < 8; w++) s += red8[w];
            slog[i] = s;
        }
        __syncthreads();
    }

    // phase B: softmax over deg edges (thread 0, deg small)
    if (t == 0) {
        float m = -1e30f;
        for (int i = 0; i < deg; i++) m = fmaxf(m, slog[i]);
        float s = 0.f;
        for (int i = 0; i < deg; i++) s += expf(slog[i] - m);
        float inv = 1.f / (s + 1e-16f);
        for (int i = 0; i < deg; i++) slog[i] = expf(slog[i] - m) * inv;
    }
    __syncthreads();

    // phase C: weighted aggregation + bias + relu + pool accumulation
    for (int a = t; a < NA; a += 256) {
        float accv = 0.f;
        for (int i = 0; i < deg; i++)
            accv += slog[i] * g_xl2[(size_t)ssrc[i] * NA + a];
        float v = accv + b2[a];
        v = v > 0.f ? v : 0.f;
        atomicAdd(&g_pooled[a], v);
    }
}

__global__ void k_final(const float* __restrict__ alpha, float* __restrict__ out,
                        int out_size) {
    __shared__ float red[32];
    int t = threadIdx.x;
    const float invN = 1.f / (float)NN;
    float m = -1e30f;
    for (int a = t; a < NA; a += 1024) m = fmaxf(m, g_pooled[a] * invN);
    for (int o = 16; o; o >>= 1) m = fmaxf(m, __shfl_xor_sync(0xffffffffu, m, o));
    if ((t & 31) == 0) red[t >> 5] = m;
    __syncthreads();
    if (t < 32) {
        float r = red[t];
        for (int o = 16; o; o >>= 1) r = fmaxf(r, __shfl_xor_sync(0xffffffffu, r, o));
        if (t == 0) red[0] = r;
    }
    __syncthreads();
    m = red[0];
    __syncthreads();
    float s = 0.f;
    for (int a = t; a < NA; a += 1024) s += expf(g_pooled[a] * invN - m);
    for (int o = 16; o; o >>= 1) s += __shfl_xor_sync(0xffffffffu, s, o);
    if ((t & 31) == 0) red[t >> 5] = s;
    __syncthreads();
    if (t < 32) {
        float r = red[t];
        for (int o = 16; o; o >>= 1) r += __shfl_xor_sync(0xffffffffu, r, o);
        if (t == 0) red[0] = r;
    }
    __syncthreads();
    float invS = 1.f / red[0];
    for (int a = t; a < NA; a += 1024)
        out[a] = expf(g_pooled[a] * invN - m) * invS;
    if (t == 0 && out_size > NA)
        out[NA] = 1.f / (1.f + expf(-alpha[0]));
}

// ---------------- launch ------------------------------------------------------
extern "C" void kernel_launch(void* const* d_in, const int* in_sizes, int n_in,
                              void* d_out, int out_size) {
    const float* x     = (const float*)d_in[0];
    const int*   ei    = (const int*)d_in[1];      // int32 (JAX default)
    const float* eattr = (const float*)d_in[2];
    const float* alpha = (const float*)d_in[3];
    const float* Wl1 = (const float*)d_in[4];
    const float* bl1 = (const float*)d_in[5];
    const float* Wr1 = (const float*)d_in[6];
    const float* br1 = (const float*)d_in[7];
    const float* We1 = (const float*)d_in[8];
    const float* att1= (const float*)d_in[9];
    const float* b1  = (const float*)d_in[10];
    const float* Wl2 = (const float*)d_in[11];
    const float* bl2 = (const float*)d_in[12];
    const float* Wr2 = (const float*)d_in[13];
    const float* br2 = (const float*)d_in[14];
    const float* We2 = (const float*)d_in[15];
    const float* att2= (const float*)d_in[16];
    const float* b2  = (const float*)d_in[17];
    float* out = (float*)d_out;

    k_init      <<<(NA + 255) / 256, 256>>>();
    k_edge_stats<<<(NE + 255) / 256, 256>>>(ei, eattr);
    k_build     <<<(E2 + 255) / 256, 256>>>(ei, eattr);
    k_scan      <<<1, 1024>>>();
    k_scatter   <<<(E2 + 255) / 256, 256>>>();
    k_gemm1     <<<dim3(NN / 16, 2), 256>>>(x, Wl1, bl1, Wr1, br1);
    k_attn1     <<<NN, 256>>>(We1, att1, b1);
    k_gemm2     <<<dim3((NA + 127) / 128, (NN + 127) / 128, 2), 256>>>(Wl2, bl2, Wr2, br2);
    k_attn2     <<<NN, 256>>>(We2, att2, b2);
    k_final     <<<1, 1024>>>(alpha, out, out_size);
}